// round 5
// baseline (speedup 1.0000x reference)
#include <cuda_runtime.h>
#include <cstdint>

// Problem dims (fixed by the reference setup)
#define BATCH   8
#define NT      1024          // N*T
#define MLANES  64            // M
#define LPTS    16            // L
#define NEMBD   128
#define EDIM    12
#define NPOS    (BATCH * NT * MLANES)   // 524288

#define ROWS_PB 8             // agent rows per block
#define POS_PB  (ROWS_PB * MLANES)      // 512 positions per block
#define TPB     256
#define CHUNK   (POS_PB / 4)  // 128 positions per warp-pair

typedef unsigned long long u64;

// ---------------------------------------------------------------------------
// packed f32x2 helpers (Blackwell)
// ---------------------------------------------------------------------------
__device__ __forceinline__ u64 pack2(float a, float b) {
    u64 r;
    asm("mov.b64 %0, {%1,%2};" : "=l"(r) : "f"(a), "f"(b));
    return r;
}
__device__ __forceinline__ void unpack2(u64 v, float& a, float& b) {
    asm("mov.b64 {%0,%1}, %2;" : "=f"(a), "=f"(b) : "l"(v));
}
__device__ __forceinline__ void fma2(u64& acc, u64 a, u64 b) {
    asm("fma.rn.f32x2 %0, %1, %2, %0;" : "+l"(acc) : "l"(a), "l"(b));
}

__device__ __forceinline__ float4 dx_at(float px, float py, float ps, float pc,
                                        float flag1, float4 q) {
    float f2 = (q.x == 0.f && q.y == 0.f && q.z == 0.f && q.w == 0.f) ? 0.f : 1.f;
    float f  = flag1 * f2;
    float dxw = px - q.x;
    float dyw = py - q.y;
    float dX = (dxw * q.w + dyw * q.z) * 0.1f * f;   // delta_x / 10
    float dY = (-dxw * q.z + dyw * q.w) * 0.1f * f;  // delta_y / 10
    float ds = (ps * q.w - pc * q.z) * f;
    float dc = (pc * q.w + ps * q.z) * f;
    return make_float4(dX, dY, ds, dc);
}

// ---------------------------------------------------------------------------
// Fused kernel: edge features (smem-local) + projection.
// ---------------------------------------------------------------------------
__global__ void __launch_bounds__(TPB, 3)
fused_kernel(const float* __restrict__ agent,
             const float* __restrict__ lane,
             const float* __restrict__ W,
             const float* __restrict__ bias,
             float* __restrict__ out) {
    __shared__ __align__(16) float4 slane[LPTS * MLANES];    // [l][m], 16 KB
    __shared__ float sagent[ROWS_PB * 8];                    // 256 B
    __shared__ __align__(16) float sedge[POS_PB * EDIM];     // 24 KB

    const int tid  = threadIdx.x;
    const size_t row0 = (size_t)blockIdx.x * ROWS_PB;        // global agent row base
    const int b = (int)(row0 >> 10);

    // ---- Phase 0: stage lane (transposed [l][m]) + agent rows ----
    const float4* lg = reinterpret_cast<const float4*>(lane) + (size_t)b * MLANES * LPTS;
#pragma unroll
    for (int k = 0; k < 4; k++) {
        int s = tid + k * 256;            // s = l*64 + m
        int l = s >> 6, m = s & 63;
        slane[s] = __ldg(lg + m * LPTS + l);
    }
    if (tid < ROWS_PB * 8)
        sagent[tid] = __ldg(agent + row0 * 8 + tid);

    // ---- Per-lane weights for 2 channels (independent of staging) ----
    const int warp = tid >> 5;
    const int lid  = tid & 31;
    const int e0   = (warp & 1) * 64 + lid * 2;   // this lane's first channel

    u64 wp0[6], wp1[6];
#pragma unroll
    for (int k = 0; k < 6; k++) {
        wp0[k] = pack2(__ldg(W + (e0 + 0) * EDIM + 2 * k), __ldg(W + (e0 + 0) * EDIM + 2 * k + 1));
        wp1[k] = pack2(__ldg(W + (e0 + 1) * EDIM + 2 * k), __ldg(W + (e0 + 1) * EDIM + 2 * k + 1));
    }
    const u64 b0 = pack2(__ldg(bias + e0 + 0), 0.f);
    const u64 b1 = pack2(__ldg(bias + e0 + 1), 0.f);

    __syncthreads();

    // ---- Phase A: edge features into smem (2 positions per thread) ----
#pragma unroll
    for (int it = 0; it < 2; it++) {
        int p = tid + it * 256;           // local position
        int r = p >> 6, m = p & 63;
        const float* ar = sagent + r * 8;
        float a0 = ar[0], a1 = ar[1], a2 = ar[2], a3 = ar[3];
        float a4 = ar[4], a5 = ar[5], a6 = ar[6], a7 = ar[7];
        float flag1 = (a0 == 0.f && a1 == 0.f && a2 == 0.f && a3 == 0.f &&
                       a4 == 0.f && a5 == 0.f && a6 == 0.f && a7 == 0.f) ? 0.f : 1.f;
        float px = a0, py = a1, ps = a3, pc = a4;

        float bestAbs = 3.4e38f;
        int   bestl   = 0;
#pragma unroll
        for (int l = 0; l < LPTS; l++) {
            float4 q = slane[l * MLANES + m];     // contiguous LDS.128, conflict-free
            float f2 = (q.x == 0.f && q.y == 0.f && q.z == 0.f && q.w == 0.f) ? 0.f : 1.f;
            float f01 = 0.1f * flag1 * f2;
            float dxw = px - q.x;
            float dyw = py - q.y;
            float aX = fabsf((dxw * q.w + dyw * q.z) * f01);
            if (aX < bestAbs) { bestAbs = aX; bestl = l; }   // strict < = first-min
        }

        float4 mp  = dx_at(px, py, ps, pc, flag1, slane[bestl * MLANES + m]);
        float4 el0 = dx_at(px, py, ps, pc, flag1, slane[0 * MLANES + m]);
        float4 elL = dx_at(px, py, ps, pc, flag1, slane[(LPTS - 1) * MLANES + m]);

        float4* ep = reinterpret_cast<float4*>(sedge + p * EDIM);   // rows 16B-aligned
        ep[0] = mp;
        ep[1] = el0;
        ep[2] = elL;
    }

    __syncthreads();

    // ---- Phase B: projection. Warp-pair owns a contiguous 128-position chunk.
    //      2-position manual unroll; edge rows via 3x LDS.128 each; pointer bumps.
    const int pair = warp >> 1;
    const ulonglong2* eptr =
        reinterpret_cast<const ulonglong2*>(sedge + pair * CHUNK * EDIM);
    float* optr = out + ((size_t)blockIdx.x * POS_PB + (size_t)pair * CHUNK) * NEMBD + e0;

#pragma unroll 1
    for (int it = 0; it < CHUNK / 2; it++) {
        // Load both positions' edge rows up front (6 independent LDS.128)
        ulonglong2 qa0 = eptr[0], qa1 = eptr[1], qa2 = eptr[2];   // position A
        ulonglong2 qb0 = eptr[3], qb1 = eptr[4], qb2 = eptr[5];   // position B
        eptr += 6;

        u64 evA[6] = { qa0.x, qa0.y, qa1.x, qa1.y, qa2.x, qa2.y };
        u64 evB[6] = { qb0.x, qb0.y, qb1.x, qb1.y, qb2.x, qb2.y };

        u64 accA0 = b0, accA1 = b1, accB0 = b0, accB1 = b1;
#pragma unroll
        for (int k = 0; k < 6; k++) {
            fma2(accA0, evA[k], wp0[k]);
            fma2(accA1, evA[k], wp1[k]);
            fma2(accB0, evB[k], wp0[k]);
            fma2(accB1, evB[k], wp1[k]);
        }

        float xa0, ya0, xa1, ya1, xb0, yb0, xb1, yb1;
        unpack2(accA0, xa0, ya0); unpack2(accA1, xa1, ya1);
        unpack2(accB0, xb0, yb0); unpack2(accB1, xb1, yb1);

        __stcs(reinterpret_cast<float2*>(optr),
               make_float2(xa0 + ya0, xa1 + ya1));
        __stcs(reinterpret_cast<float2*>(optr + NEMBD),
               make_float2(xb0 + yb0, xb1 + yb1));
        optr += 2 * NEMBD;
    }
}

// ---------------------------------------------------------------------------
// Launch: inputs in metadata order: agent, lane, W, b. Output fp32.
// ---------------------------------------------------------------------------
extern "C" void kernel_launch(void* const* d_in, const int* in_sizes, int n_in,
                              void* d_out, int out_size) {
    const float* agent = (const float*)d_in[0];
    const float* lane  = (const float*)d_in[1];
    const float* W     = (const float*)d_in[2];
    const float* bias  = (const float*)d_in[3];
    float* out = (float*)d_out;

    fused_kernel<<<NPOS / POS_PB, TPB>>>(agent, lane, W, bias, out);
}

// round 7
// speedup vs baseline: 1.0159x; 1.0159x over previous
#include <cuda_runtime.h>
#include <cstdint>

// Problem dims (fixed by the reference setup)
#define BATCH   8
#define NT      1024          // N*T
#define MLANES  64            // M
#define LPTS    16            // L
#define NEMBD   128
#define EDIM    12
#define NPOS    (BATCH * NT * MLANES)   // 524288

#define ROWS_PB 8             // agent rows per block
#define POS_PB  (ROWS_PB * MLANES)      // 512 positions per block
#define TPB     256
#define CHUNK   (POS_PB / 4)  // 128 positions per warp-pair

typedef unsigned long long u64;

// ---------------------------------------------------------------------------
// packed f32x2 helpers (Blackwell)
// ---------------------------------------------------------------------------
__device__ __forceinline__ u64 pack2(float a, float b) {
    u64 r;
    asm("mov.b64 %0, {%1,%2};" : "=l"(r) : "f"(a), "f"(b));
    return r;
}
__device__ __forceinline__ void unpack2(u64 v, float& a, float& b) {
    asm("mov.b64 {%0,%1}, %2;" : "=f"(a), "=f"(b) : "l"(v));
}
__device__ __forceinline__ void fma2(u64& acc, u64 a, u64 b) {
    asm("fma.rn.f32x2 %0, %1, %2, %0;" : "+l"(acc) : "l"(a), "l"(b));
}

__device__ __forceinline__ float4 dx_at(float px, float py, float ps, float pc,
                                        float flag1, float4 q) {
    float f2 = (q.x == 0.f && q.y == 0.f && q.z == 0.f && q.w == 0.f) ? 0.f : 1.f;
    float f  = flag1 * f2;
    float dxw = px - q.x;
    float dyw = py - q.y;
    float dX = (dxw * q.w + dyw * q.z) * 0.1f * f;   // delta_x / 10
    float dY = (-dxw * q.z + dyw * q.w) * 0.1f * f;  // delta_y / 10
    float ds = (ps * q.w - pc * q.z) * f;
    float dc = (pc * q.w + ps * q.z) * f;
    return make_float4(dX, dY, ds, dc);
}

// ---------------------------------------------------------------------------
// Fused kernel: edge features (smem-local) + projection.
// Block: 256 threads, 8 agent rows x 64 lane-segments = 512 positions.
// ---------------------------------------------------------------------------
__global__ void __launch_bounds__(TPB, 3)
fused_kernel(const float* __restrict__ agent,
             const float* __restrict__ lane,
             const float* __restrict__ W,
             const float* __restrict__ bias,
             float* __restrict__ out) {
    __shared__ __align__(16) float4 slane[LPTS * MLANES];    // [l][m], 16 KB
    __shared__ float sagent[ROWS_PB * 8];                    // 256 B
    __shared__ __align__(16) float sedge[POS_PB * EDIM];     // 24 KB

    const int tid  = threadIdx.x;
    const size_t row0 = (size_t)blockIdx.x * ROWS_PB;        // global agent row base
    const int b = (int)(row0 >> 10);

    // ---- Phase 0: stage lane (transposed [l][m]) + agent rows ----
    const float4* lg = reinterpret_cast<const float4*>(lane) + (size_t)b * MLANES * LPTS;
#pragma unroll
    for (int k = 0; k < 4; k++) {
        int s = tid + k * 256;            // s = l*64 + m
        int l = s >> 6, m = s & 63;
        slane[s] = __ldg(lg + m * LPTS + l);
    }
    if (tid < ROWS_PB * 8)
        sagent[tid] = __ldg(agent + row0 * 8 + tid);

    // ---- Per-lane weights for 2 channels (independent of staging) ----
    const int warp = tid >> 5;
    const int lid  = tid & 31;
    const int e0   = (warp & 1) * 64 + lid * 2;   // this lane's first channel

    u64 wp0[6], wp1[6];
#pragma unroll
    for (int k = 0; k < 6; k++) {
        wp0[k] = pack2(__ldg(W + (e0 + 0) * EDIM + 2 * k), __ldg(W + (e0 + 0) * EDIM + 2 * k + 1));
        wp1[k] = pack2(__ldg(W + (e0 + 1) * EDIM + 2 * k), __ldg(W + (e0 + 1) * EDIM + 2 * k + 1));
    }
    const u64 b0 = pack2(__ldg(bias + e0 + 0), 0.f);
    const u64 b1 = pack2(__ldg(bias + e0 + 1), 0.f);

    __syncthreads();

    // ---- Phase A: edge features into smem (2 positions per thread) ----
#pragma unroll
    for (int it = 0; it < 2; it++) {
        int p = tid + it * 256;           // local position
        int r = p >> 6, m = p & 63;
        const float* ar = sagent + r * 8;
        float a0 = ar[0], a1 = ar[1], a2 = ar[2], a3 = ar[3];
        float a4 = ar[4], a5 = ar[5], a6 = ar[6], a7 = ar[7];
        float flag1 = (a0 == 0.f && a1 == 0.f && a2 == 0.f && a3 == 0.f &&
                       a4 == 0.f && a5 == 0.f && a6 == 0.f && a7 == 0.f) ? 0.f : 1.f;
        float px = a0, py = a1, ps = a3, pc = a4;

        float bestAbs = 3.4e38f;
        int   bestl   = 0;
#pragma unroll
        for (int l = 0; l < LPTS; l++) {
            float4 q = slane[l * MLANES + m];     // contiguous LDS.128, conflict-free
            float f2 = (q.x == 0.f && q.y == 0.f && q.z == 0.f && q.w == 0.f) ? 0.f : 1.f;
            float f01 = 0.1f * flag1 * f2;
            float dxw = px - q.x;
            float dyw = py - q.y;
            float aX = fabsf((dxw * q.w + dyw * q.z) * f01);
            if (aX < bestAbs) { bestAbs = aX; bestl = l; }   // strict < = first-min
        }

        float4 mp  = dx_at(px, py, ps, pc, flag1, slane[bestl * MLANES + m]);
        float4 el0 = dx_at(px, py, ps, pc, flag1, slane[0 * MLANES + m]);
        float4 elL = dx_at(px, py, ps, pc, flag1, slane[(LPTS - 1) * MLANES + m]);

        float4* ep = reinterpret_cast<float4*>(sedge + p * EDIM);   // rows 16B-aligned
        ep[0] = mp;
        ep[1] = el0;
        ep[2] = elL;
    }

    __syncthreads();

    // ---- Phase B: projection. Warp-pair owns a contiguous 128-position chunk.
    //      2-position manual unroll; edge rows via 3x LDS.128 each; pointer bumps.
    const int pair = warp >> 1;
    const ulonglong2* eptr =
        reinterpret_cast<const ulonglong2*>(sedge + pair * CHUNK * EDIM);
    float* optr = out + ((size_t)blockIdx.x * POS_PB + (size_t)pair * CHUNK) * NEMBD + e0;

#pragma unroll 1
    for (int it = 0; it < CHUNK / 2; it++) {
        // Load both positions' edge rows up front (6 independent LDS.128)
        ulonglong2 qa0 = eptr[0], qa1 = eptr[1], qa2 = eptr[2];   // position A
        ulonglong2 qb0 = eptr[3], qb1 = eptr[4], qb2 = eptr[5];   // position B
        eptr += 6;

        u64 evA[6] = { qa0.x, qa0.y, qa1.x, qa1.y, qa2.x, qa2.y };
        u64 evB[6] = { qb0.x, qb0.y, qb1.x, qb1.y, qb2.x, qb2.y };

        u64 accA0 = b0, accA1 = b1, accB0 = b0, accB1 = b1;
#pragma unroll
        for (int k = 0; k < 6; k++) {
            fma2(accA0, evA[k], wp0[k]);
            fma2(accA1, evA[k], wp1[k]);
            fma2(accB0, evB[k], wp0[k]);
            fma2(accB1, evB[k], wp1[k]);
        }

        float xa0, ya0, xa1, ya1, xb0, yb0, xb1, yb1;
        unpack2(accA0, xa0, ya0); unpack2(accA1, xa1, ya1);
        unpack2(accB0, xb0, yb0); unpack2(accB1, xb1, yb1);

        __stcs(reinterpret_cast<float2*>(optr),
               make_float2(xa0 + ya0, xa1 + ya1));
        __stcs(reinterpret_cast<float2*>(optr + NEMBD),
               make_float2(xb0 + yb0, xb1 + yb1));
        optr += 2 * NEMBD;
    }
}

// ---------------------------------------------------------------------------
// Launch: inputs in metadata order: agent, lane, W, b. Output fp32.
// ---------------------------------------------------------------------------
extern "C" void kernel_launch(void* const* d_in, const int* in_sizes, int n_in,
                              void* d_out, int out_size) {
    const float* agent = (const float*)d_in[0];
    const float* lane  = (const float*)d_in[1];
    const float* W     = (const float*)d_in[2];
    const float* bias  = (const float*)d_in[3];
    float* out = (float*)d_out;

    fused_kernel<<<NPOS / POS_PB, TPB>>>(agent, lane, W, bias, out);
}